// round 4
// baseline (speedup 1.0000x reference)
#include <cuda_runtime.h>
#include <math.h>
#include <stdint.h>

#define D 768
#define H 12
#define HD 64
#define DFF 3072
#define QKV3 2304
#define MAXTOK 8192
#define S_MAX 1024

// ---------------- scratch (static device globals; no allocation) ----------------
__device__ float g_ln[MAXTOK * D];
__device__ float g_qkv[MAXTOK * QKV3];
__device__ float g_attn[MAXTOK * D];
__device__ float g_x2[MAXTOK * D];
__device__ float g_h[MAXTOK * D];
__device__ float g_m[MAXTOK * DFF];

// ---------------- LayerNorm: one block per token row ----------------
__global__ __launch_bounds__(256) void ln_kernel(
    const float* __restrict__ x, const float* __restrict__ g,
    const float* __restrict__ b, float* __restrict__ out)
{
    int row = blockIdx.x;
    const float* xr = x + (size_t)row * D;
    int t = threadIdx.x;

    float v0 = xr[t], v1 = xr[t + 256], v2 = xr[t + 512];
    float s = v0 + v1 + v2;
    float sq = v0 * v0 + v1 * v1 + v2 * v2;

    #pragma unroll
    for (int off = 16; off > 0; off >>= 1) {
        s  += __shfl_xor_sync(0xFFFFFFFFu, s, off);
        sq += __shfl_xor_sync(0xFFFFFFFFu, sq, off);
    }
    __shared__ float ss[8], ssq[8];
    int wid = t >> 5, lid = t & 31;
    if (lid == 0) { ss[wid] = s; ssq[wid] = sq; }
    __syncthreads();
    if (wid == 0) {
        float a = (lid < 8) ? ss[lid] : 0.f;
        float aq = (lid < 8) ? ssq[lid] : 0.f;
        #pragma unroll
        for (int off = 4; off > 0; off >>= 1) {
            a  += __shfl_xor_sync(0xFFFFFFFFu, a, off);
            aq += __shfl_xor_sync(0xFFFFFFFFu, aq, off);
        }
        if (lid == 0) { ss[0] = a; ssq[0] = aq; }
    }
    __syncthreads();
    float mean = ss[0] * (1.0f / D);
    float var = ssq[0] * (1.0f / D) - mean * mean;
    float rstd = rsqrtf(var + 1e-6f);

    float* orow = out + (size_t)row * D;
    orow[t]       = (v0 - mean) * rstd * g[t]       + b[t];
    orow[t + 256] = (v1 - mean) * rstd * g[t + 256] + b[t + 256];
    orow[t + 512] = (v2 - mean) * rstd * g[t + 512] + b[t + 512];
}

// ---------------- tf32 helpers ----------------
__device__ __forceinline__ uint32_t f2tf(float f) {
    uint32_t r;
    asm("cvt.rna.tf32.f32 %0, %1;" : "=r"(r) : "f"(f));
    return r;
}

__device__ __forceinline__ void mma_tf32(
    float& c0, float& c1, float& c2, float& c3,
    uint32_t a0, uint32_t a1, uint32_t a2, uint32_t a3,
    uint32_t b0, uint32_t b1)
{
    asm volatile(
        "mma.sync.aligned.m16n8k8.row.col.f32.tf32.tf32.f32 "
        "{%0,%1,%2,%3}, {%4,%5,%6,%7}, {%8,%9}, {%0,%1,%2,%3};"
        : "+f"(c0), "+f"(c1), "+f"(c2), "+f"(c3)
        : "r"(a0), "r"(a1), "r"(a2), "r"(a3), "r"(b0), "r"(b1));
}

// ---------------- tensor-core GEMM: C = A[MxK]*B[KxN] + bias (+res / gelu) ----------------
// Block tile 128x128x32, 8 warps (4M x 2N), warp tile 32x64.
// Smem holds tiles in FRAGMENT ORDER:
//   As2[k][m']  m' = (m%8)*16 + m/8  -> a-frags for both mi = one LDS.128
//   Bs2[k][n']  n' = (n%8)*16 + n/8  -> b-frags for 4 ni  = one LDS.128
// Row stride 132 (=4 mod 32) -> all frag LDS.128 phases conflict-free.
#define SPAD 132

template <int EPI>
__global__ __launch_bounds__(256, 2) void gemm_mma(
    const float* __restrict__ A, const float* __restrict__ Bm,
    const float* __restrict__ bias, const float* __restrict__ res,
    float* __restrict__ C, int M, int N, int K)
{
    __shared__ uint32_t As2[32 * SPAD];
    __shared__ uint32_t Bs2[32 * SPAD];

    int tid  = threadIdx.x;
    int warp = tid >> 5, lane = tid & 31;
    int wm = (warp >> 1) * 32;
    int wn = (warp & 1) * 64;
    int g  = lane >> 2;
    int t4 = lane & 3;
    int wmo = wm >> 3;        // {0,4,8,12}
    int wno = wn >> 3;        // {0,8}

    int bm = blockIdx.y * 128;
    int bn = blockIdx.x * 128;

    // ---- staging indices ----
    // A: thread -> row m = tid/2, float4 group fbase = (tid&1)*4  (k = (fbase+i)*4)
    int am = tid >> 1;
    int afb = (tid & 1) * 4;
    int gaRow = bm + am; if (gaRow >= M) gaRow = M - 1;
    const float* Ag = A + (size_t)gaRow * K + afb * 4;
    int amp = (am & 7) * 16 + (am >> 3);
    // B: thread -> k row = tid/8, nbase = (tid&7)*16
    int bk = tid >> 3;
    int bnb = (tid & 7) * 16;
    const float* Bg = Bm + (size_t)bk * N + bn + bnb;

    float acc[2][8][4];
    #pragma unroll
    for (int mi = 0; mi < 2; mi++)
        #pragma unroll
        for (int ni = 0; ni < 8; ni++)
            #pragma unroll
            for (int r = 0; r < 4; r++) acc[mi][ni][r] = 0.f;

    // prefetch k-tile 0
    float4 pa[4], pb[4];
    #pragma unroll
    for (int i = 0; i < 4; i++) {
        pa[i] = *(const float4*)(Ag + i * 4);
        pb[i] = *(const float4*)(Bg + i * 4);
    }

    for (int k0 = 0; k0 < K; k0 += 32) {
        __syncthreads();
        // store A tile: transpose+permute, tf32
        #pragma unroll
        for (int i = 0; i < 4; i++) {
            int krow = (afb + i) * 4;
            As2[(krow + 0) * SPAD + amp] = f2tf(pa[i].x);
            As2[(krow + 1) * SPAD + amp] = f2tf(pa[i].y);
            As2[(krow + 2) * SPAD + amp] = f2tf(pa[i].z);
            As2[(krow + 3) * SPAD + amp] = f2tf(pa[i].w);
        }
        // store B tile: permute cols, tf32
        #pragma unroll
        for (int i = 0; i < 4; i++) {
            float v[4] = {pb[i].x, pb[i].y, pb[i].z, pb[i].w};
            #pragma unroll
            for (int j = 0; j < 4; j++) {
                int n = bnb + 4 * i + j;
                Bs2[bk * SPAD + (n & 7) * 16 + (n >> 3)] = f2tf(v[j]);
            }
        }
        __syncthreads();

        if (k0 + 32 < K) {
            #pragma unroll
            for (int i = 0; i < 4; i++) {
                pa[i] = *(const float4*)(Ag + k0 + 32 + i * 4);
                pb[i] = *(const float4*)(Bg + (size_t)(k0 + 32) * N + i * 4);
            }
        }

        #pragma unroll
        for (int kk = 0; kk < 32; kk += 8) {
            uint4 aLo = *(const uint4*)&As2[(kk + t4) * SPAD + g * 16 + wmo];
            uint4 aHi = *(const uint4*)&As2[(kk + 4 + t4) * SPAD + g * 16 + wmo];
            uint4 b0a = *(const uint4*)&Bs2[(kk + t4) * SPAD + g * 16 + wno];
            uint4 b0b = *(const uint4*)&Bs2[(kk + t4) * SPAD + g * 16 + wno + 4];
            uint4 b1a = *(const uint4*)&Bs2[(kk + 4 + t4) * SPAD + g * 16 + wno];
            uint4 b1b = *(const uint4*)&Bs2[(kk + 4 + t4) * SPAD + g * 16 + wno + 4];

            uint32_t b0[8] = {b0a.x, b0a.y, b0a.z, b0a.w, b0b.x, b0b.y, b0b.z, b0b.w};
            uint32_t b1[8] = {b1a.x, b1a.y, b1a.z, b1a.w, b1b.x, b1b.y, b1b.z, b1b.w};

            #pragma unroll
            for (int ni = 0; ni < 8; ni++) {
                mma_tf32(acc[0][ni][0], acc[0][ni][1], acc[0][ni][2], acc[0][ni][3],
                         aLo.x, aLo.y, aHi.x, aHi.y, b0[ni], b1[ni]);
                mma_tf32(acc[1][ni][0], acc[1][ni][1], acc[1][ni][2], acc[1][ni][3],
                         aLo.z, aLo.w, aHi.z, aHi.w, b0[ni], b1[ni]);
            }
        }
    }

    // ---- epilogue ----
    #pragma unroll
    for (int mi = 0; mi < 2; mi++) {
        #pragma unroll
        for (int half = 0; half < 2; half++) {
            int row = bm + wm + mi * 16 + half * 8 + g;
            if (row >= M) continue;
            #pragma unroll
            for (int ni = 0; ni < 8; ni++) {
                int col = bn + wn + ni * 8 + t4 * 2;
                float v0 = acc[mi][ni][half * 2 + 0] + bias[col];
                float v1 = acc[mi][ni][half * 2 + 1] + bias[col + 1];
                if (EPI == 1) {
                    v0 += res[(size_t)row * N + col];
                    v1 += res[(size_t)row * N + col + 1];
                }
                if (EPI == 2) {
                    v0 = 0.5f * v0 * (1.0f + erff(v0 * 0.70710678118654752f));
                    v1 = 0.5f * v1 * (1.0f + erff(v1 * 0.70710678118654752f));
                }
                float2 o; o.x = v0; o.y = v1;
                *(float2*)(C + (size_t)row * N + col) = o;
            }
        }
    }
}

// ---------------- tensor-core flash attention (tf32, max-free softmax) ----------------
#define KT 32
#define QS 68
#define PS 36

__global__ __launch_bounds__(128) void attn_mma(
    const float* __restrict__ qkv, const int* __restrict__ cu,
    float* __restrict__ out)
{
    __shared__ uint32_t Qs[64 * QS];
    __shared__ uint32_t Ks[KT * QS];
    __shared__ uint32_t Vs[KT * QS];
    __shared__ uint32_t Ps[4][16 * PS];

    int b = blockIdx.z, h = blockIdx.y, qt = blockIdx.x;
    int s0 = cu[b];
    int len = cu[b + 1] - s0;
    if (qt * 64 >= len) return;

    int tid = threadIdx.x;
    int warp = tid >> 5, lane = tid & 31;
    int g = lane >> 2, t4 = lane & 3;

    {
        int qr = tid >> 1;
        int qc = (tid & 1) * 32;
        int gq = qt * 64 + qr; if (gq >= len) gq = len - 1;
        const float* src = qkv + (size_t)(s0 + gq) * QKV3 + h * HD + qc;
        uint32_t* dst = &Qs[qr * QS + qc];
        #pragma unroll
        for (int i = 0; i < 8; i++) {
            float4 v = *(const float4*)(src + i * 4);
            dst[i * 4 + 0] = f2tf(v.x * 0.125f);
            dst[i * 4 + 1] = f2tf(v.y * 0.125f);
            dst[i * 4 + 2] = f2tf(v.z * 0.125f);
            dst[i * 4 + 3] = f2tf(v.w * 0.125f);
        }
    }
    __syncthreads();

    uint32_t qf[8][4];
    int wq = warp * 16;
    #pragma unroll
    for (int ks = 0; ks < 8; ks++) {
        qf[ks][0] = Qs[(wq + g) * QS + ks * 8 + t4];
        qf[ks][1] = Qs[(wq + g + 8) * QS + ks * 8 + t4];
        qf[ks][2] = Qs[(wq + g) * QS + ks * 8 + 4 + t4];
        qf[ks][3] = Qs[(wq + g + 8) * QS + ks * 8 + 4 + t4];
    }

    float oa[8][4];
    #pragma unroll
    for (int vn = 0; vn < 8; vn++)
        #pragma unroll
        for (int r = 0; r < 4; r++) oa[vn][r] = 0.f;
    float lp0 = 0.f, lp1 = 0.f;

    int krow = tid >> 2;
    int kcol = (tid & 3) * 16;
    int ntile = (len + KT - 1) / KT;

    float4 pk[4], pv[4];
    {
        int gk = krow; if (gk >= len) gk = len - 1;
        const float* base = qkv + (size_t)(s0 + gk) * QKV3 + h * HD + kcol;
        #pragma unroll
        for (int i = 0; i < 4; i++) {
            pk[i] = *(const float4*)(base + D + i * 4);
            pv[i] = *(const float4*)(base + 2 * D + i * 4);
        }
    }

    for (int kt = 0; kt < ntile; kt++) {
        __syncthreads();
        {
            uint32_t* kd = &Ks[krow * QS + kcol];
            uint32_t* vd = &Vs[krow * QS + kcol];
            #pragma unroll
            for (int i = 0; i < 4; i++) {
                kd[i * 4 + 0] = f2tf(pk[i].x); kd[i * 4 + 1] = f2tf(pk[i].y);
                kd[i * 4 + 2] = f2tf(pk[i].z); kd[i * 4 + 3] = f2tf(pk[i].w);
                vd[i * 4 + 0] = f2tf(pv[i].x); vd[i * 4 + 1] = f2tf(pv[i].y);
                vd[i * 4 + 2] = f2tf(pv[i].z); vd[i * 4 + 3] = f2tf(pv[i].w);
            }
        }
        __syncthreads();

        if (kt + 1 < ntile) {
            int gk = (kt + 1) * KT + krow; if (gk >= len) gk = len - 1;
            const float* base = qkv + (size_t)(s0 + gk) * QKV3 + h * HD + kcol;
            #pragma unroll
            for (int i = 0; i < 4; i++) {
                pk[i] = *(const float4*)(base + D + i * 4);
                pv[i] = *(const float4*)(base + 2 * D + i * 4);
            }
        }

        float sa[4][4];
        #pragma unroll
        for (int kn = 0; kn < 4; kn++)
            #pragma unroll
            for (int r = 0; r < 4; r++) sa[kn][r] = 0.f;

        #pragma unroll
        for (int ks = 0; ks < 8; ks++) {
            #pragma unroll
            for (int kn = 0; kn < 4; kn++) {
                uint32_t b0 = Ks[(kn * 8 + g) * QS + ks * 8 + t4];
                uint32_t b1 = Ks[(kn * 8 + g) * QS + ks * 8 + 4 + t4];
                mma_tf32(sa[kn][0], sa[kn][1], sa[kn][2], sa[kn][3],
                         qf[ks][0], qf[ks][1], qf[ks][2], qf[ks][3], b0, b1);
            }
        }

        uint32_t* pw = Ps[warp];
        #pragma unroll
        for (int kn = 0; kn < 4; kn++) {
            int c0 = kt * KT + kn * 8 + 2 * t4;
            float p0 = (c0     < len) ? __expf(sa[kn][0]) : 0.f;
            float p1 = (c0 + 1 < len) ? __expf(sa[kn][1]) : 0.f;
            float p2 = (c0     < len) ? __expf(sa[kn][2]) : 0.f;
            float p3 = (c0 + 1 < len) ? __expf(sa[kn][3]) : 0.f;
            lp0 += p0 + p1;
            lp1 += p2 + p3;
            pw[g * PS + kn * 8 + 2 * t4]       = f2tf(p0);
            pw[g * PS + kn * 8 + 2 * t4 + 1]   = f2tf(p1);
            pw[(g + 8) * PS + kn * 8 + 2 * t4]     = f2tf(p2);
            pw[(g + 8) * PS + kn * 8 + 2 * t4 + 1] = f2tf(p3);
        }
        __syncwarp();

        #pragma unroll
        for (int ks = 0; ks < 4; ks++) {
            uint32_t a0 = pw[g * PS + ks * 8 + t4];
            uint32_t a1 = pw[(g + 8) * PS + ks * 8 + t4];
            uint32_t a2 = pw[g * PS + ks * 8 + 4 + t4];
            uint32_t a3 = pw[(g + 8) * PS + ks * 8 + 4 + t4];
            #pragma unroll
            for (int vn = 0; vn < 8; vn++) {
                uint32_t b0 = Vs[(ks * 8 + t4) * QS + vn * 8 + g];
                uint32_t b1 = Vs[(ks * 8 + 4 + t4) * QS + vn * 8 + g];
                mma_tf32(oa[vn][0], oa[vn][1], oa[vn][2], oa[vn][3],
                         a0, a1, a2, a3, b0, b1);
            }
        }
        __syncwarp();
    }

    lp0 += __shfl_xor_sync(0xFFFFFFFFu, lp0, 1);
    lp0 += __shfl_xor_sync(0xFFFFFFFFu, lp0, 2);
    lp1 += __shfl_xor_sync(0xFFFFFFFFu, lp1, 1);
    lp1 += __shfl_xor_sync(0xFFFFFFFFu, lp1, 2);
    float inv0 = 1.f / lp0, inv1 = 1.f / lp1;

    int q0 = qt * 64 + wq + g;
    int q1 = q0 + 8;
    if (q0 < len) {
        float* op = out + (size_t)(s0 + q0) * D + h * HD;
        #pragma unroll
        for (int vn = 0; vn < 8; vn++) {
            float2 v; v.x = oa[vn][0] * inv0; v.y = oa[vn][1] * inv0;
            *(float2*)(op + vn * 8 + 2 * t4) = v;
        }
    }
    if (q1 < len) {
        float* op = out + (size_t)(s0 + q1) * D + h * HD;
        #pragma unroll
        for (int vn = 0; vn < 8; vn++) {
            float2 v; v.x = oa[vn][2] * inv1; v.y = oa[vn][3] * inv1;
            *(float2*)(op + vn * 8 + 2 * t4) = v;
        }
    }
}

// ---------------- launch ----------------
extern "C" void kernel_launch(void* const* d_in, const int* in_sizes, int n_in,
                              void* d_out, int out_size)
{
    const float* x     = (const float*)d_in[0];
    const int*   cu    = (const int*)  d_in[1];
    const float* g1    = (const float*)d_in[2];
    const float* beta1 = (const float*)d_in[3];
    const float* Wqkv  = (const float*)d_in[4];
    const float* bqkv  = (const float*)d_in[5];
    const float* Wo    = (const float*)d_in[6];
    const float* bo    = (const float*)d_in[7];
    const float* g2    = (const float*)d_in[8];
    const float* beta2 = (const float*)d_in[9];
    const float* W1    = (const float*)d_in[10];
    const float* bfc1  = (const float*)d_in[11];
    const float* W2    = (const float*)d_in[12];
    const float* bfc2  = (const float*)d_in[13];
    float* out = (float*)d_out;

    int total = in_sizes[0] / D;
    int B = in_sizes[1] - 1;

    float *p_ln, *p_qkv, *p_attn, *p_x2, *p_h, *p_m;
    cudaGetSymbolAddress((void**)&p_ln,   g_ln);
    cudaGetSymbolAddress((void**)&p_qkv,  g_qkv);
    cudaGetSymbolAddress((void**)&p_attn, g_attn);
    cudaGetSymbolAddress((void**)&p_x2,   g_x2);
    cudaGetSymbolAddress((void**)&p_h,    g_h);
    cudaGetSymbolAddress((void**)&p_m,    g_m);

    int mtiles = (total + 127) / 128;

    ln_kernel<<<total, 256>>>(x, g1, beta1, p_ln);
    gemm_mma<0><<<dim3(QKV3 / 128, mtiles), 256>>>(p_ln, Wqkv, bqkv, nullptr, p_qkv, total, QKV3, D);
    attn_mma<<<dim3(S_MAX / 64, H, B), 128>>>(p_qkv, cu, p_attn);
    gemm_mma<1><<<dim3(D / 128, mtiles), 256>>>(p_attn, Wo, bo, x, p_x2, total, D, D);
    ln_kernel<<<total, 256>>>(p_x2, g2, beta2, p_h);
    gemm_mma<2><<<dim3(DFF / 128, mtiles), 256>>>(p_h, W1, bfc1, nullptr, p_m, total, DFF, D);
    gemm_mma<1><<<dim3(D / 128, mtiles), 256>>>(p_m, W2, bfc2, p_x2, out, total, D, DFF);
}

// round 5
// speedup vs baseline: 1.5821x; 1.5821x over previous
#include <cuda_runtime.h>
#include <math.h>
#include <stdint.h>

#define D 768
#define H 12
#define HD 64
#define DFF 3072
#define QKV3 2304
#define MAXTOK 8192
#define S_MAX 1024

// ---------------- scratch (static device globals; no allocation) ----------------
__device__ float g_ln[MAXTOK * D];
__device__ float g_qkv[MAXTOK * QKV3];
__device__ float g_attn[MAXTOK * D];
__device__ float g_x2[MAXTOK * D];
__device__ float g_h[MAXTOK * D];
__device__ float g_m[MAXTOK * DFF];

// ---------------- LayerNorm: one block per token row ----------------
__global__ __launch_bounds__(256) void ln_kernel(
    const float* __restrict__ x, const float* __restrict__ g,
    const float* __restrict__ b, float* __restrict__ out)
{
    int row = blockIdx.x;
    const float* xr = x + (size_t)row * D;
    int t = threadIdx.x;

    float v0 = xr[t], v1 = xr[t + 256], v2 = xr[t + 512];
    float s = v0 + v1 + v2;
    float sq = v0 * v0 + v1 * v1 + v2 * v2;

    #pragma unroll
    for (int off = 16; off > 0; off >>= 1) {
        s  += __shfl_xor_sync(0xFFFFFFFFu, s, off);
        sq += __shfl_xor_sync(0xFFFFFFFFu, sq, off);
    }
    __shared__ float ss[8], ssq[8];
    int wid = t >> 5, lid = t & 31;
    if (lid == 0) { ss[wid] = s; ssq[wid] = sq; }
    __syncthreads();
    if (wid == 0) {
        float a = (lid < 8) ? ss[lid] : 0.f;
        float aq = (lid < 8) ? ssq[lid] : 0.f;
        #pragma unroll
        for (int off = 4; off > 0; off >>= 1) {
            a  += __shfl_xor_sync(0xFFFFFFFFu, a, off);
            aq += __shfl_xor_sync(0xFFFFFFFFu, aq, off);
        }
        if (lid == 0) { ss[0] = a; ssq[0] = aq; }
    }
    __syncthreads();
    float mean = ss[0] * (1.0f / D);
    float var = ssq[0] * (1.0f / D) - mean * mean;
    float rstd = rsqrtf(var + 1e-6f);

    float* orow = out + (size_t)row * D;
    orow[t]       = (v0 - mean) * rstd * g[t]       + b[t];
    orow[t + 256] = (v1 - mean) * rstd * g[t + 256] + b[t + 256];
    orow[t + 512] = (v2 - mean) * rstd * g[t + 512] + b[t + 512];
}

// ---------------- tf32 / cp.async helpers ----------------
__device__ __forceinline__ uint32_t f2tf(float f) {
    uint32_t r;
    asm("cvt.rna.tf32.f32 %0, %1;" : "=r"(r) : "f"(f));
    return r;
}

__device__ __forceinline__ void mma_tf32(
    float& c0, float& c1, float& c2, float& c3,
    uint32_t a0, uint32_t a1, uint32_t a2, uint32_t a3,
    uint32_t b0, uint32_t b1)
{
    asm volatile(
        "mma.sync.aligned.m16n8k8.row.col.f32.tf32.tf32.f32 "
        "{%0,%1,%2,%3}, {%4,%5,%6,%7}, {%8,%9}, {%0,%1,%2,%3};"
        : "+f"(c0), "+f"(c1), "+f"(c2), "+f"(c3)
        : "r"(a0), "r"(a1), "r"(a2), "r"(a3), "r"(b0), "r"(b1));
}

__device__ __forceinline__ void cpa16(uint32_t dst, const void* src) {
    asm volatile("cp.async.cg.shared.global [%0], [%1], 16;" :: "r"(dst), "l"(src));
}
#define CP_COMMIT asm volatile("cp.async.commit_group;")
#define CP_WAIT(n) asm volatile("cp.async.wait_group %0;" :: "n"(n))

// ---------------- tensor-core GEMM (R3 layout + cp.async double buffer) ----------------
// Block tile 128x128x16, 8 warps (4M x 2N), warp tile 32x64.
// Tiles land in smem as raw fp32 bits; mma.tf32 truncates (CUTLASS fastpath).
#define APAD 20    // A smem row stride: conflict-free frag LDS
#define BPAD 136   // B smem row stride: conflict-free frag LDS

template <int EPI>
__global__ __launch_bounds__(256, 2) void gemm_mma(
    const float* __restrict__ A, const float* __restrict__ Bm,
    const float* __restrict__ bias, const float* __restrict__ res,
    float* __restrict__ C, int M, int N, int K)
{
    __shared__ uint32_t As[2][128 * APAD];
    __shared__ uint32_t Bs[2][16 * BPAD];

    int tid  = threadIdx.x;
    int warp = tid >> 5, lane = tid & 31;
    int wm = (warp >> 1) * 32;
    int wn = (warp & 1) * 64;
    int g  = lane >> 2;
    int t4 = lane & 3;

    int bm = blockIdx.y * 128;
    int bn = blockIdx.x * 128;

    // A: thread -> row tid/2, 8 floats starting at (tid&1)*8
    int aRow = tid >> 1;
    int aCol = (tid & 1) * 8;
    int gaRow = bm + aRow; if (gaRow >= M) gaRow = M - 1;
    const float* Ag = A + (size_t)gaRow * K + aCol;
    // B: thread -> k-row tid/16, 8 floats starting at (tid&15)*8
    int bRow = tid >> 4;
    int bCol = (tid & 15) * 8;
    const float* Bg = Bm + (size_t)bRow * N + bn + bCol;

    uint32_t aDst = (uint32_t)__cvta_generic_to_shared(&As[0][aRow * APAD + aCol]);
    uint32_t bDst = (uint32_t)__cvta_generic_to_shared(&Bs[0][bRow * BPAD + bCol]);
    const uint32_t ABUF = 128 * APAD * 4;
    const uint32_t BBUF = 16 * BPAD * 4;

    float acc[2][8][4];
    #pragma unroll
    for (int mi = 0; mi < 2; mi++)
        #pragma unroll
        for (int ni = 0; ni < 8; ni++)
            #pragma unroll
            for (int r = 0; r < 4; r++) acc[mi][ni][r] = 0.f;

    // prologue: tile 0 -> buf 0
    cpa16(aDst, Ag);      cpa16(aDst + 16, Ag + 4);
    cpa16(bDst, Bg);      cpa16(bDst + 16, Bg + 4);
    CP_COMMIT;

    int T = K >> 4;
    for (int t = 0; t < T; t++) {
        if (t + 1 < T) {
            uint32_t bo = ((t + 1) & 1);
            cpa16(aDst + bo * ABUF,      Ag + (t + 1) * 16);
            cpa16(aDst + bo * ABUF + 16, Ag + (t + 1) * 16 + 4);
            cpa16(bDst + bo * BBUF,      Bg + (size_t)(t + 1) * 16 * N);
            cpa16(bDst + bo * BBUF + 16, Bg + (size_t)(t + 1) * 16 * N + 4);
            CP_COMMIT;
            CP_WAIT(1);
        } else {
            CP_WAIT(0);
        }
        __syncthreads();

        const uint32_t* Asb = As[t & 1];
        const uint32_t* Bsb = Bs[t & 1];

        #pragma unroll
        for (int kk = 0; kk < 16; kk += 8) {
            uint32_t af[2][4];
            #pragma unroll
            for (int mi = 0; mi < 2; mi++) {
                int r0 = wm + mi * 16 + g;
                af[mi][0] = Asb[r0 * APAD + kk + t4];
                af[mi][1] = Asb[(r0 + 8) * APAD + kk + t4];
                af[mi][2] = Asb[r0 * APAD + kk + 4 + t4];
                af[mi][3] = Asb[(r0 + 8) * APAD + kk + 4 + t4];
            }
            uint32_t bf[8][2];
            #pragma unroll
            for (int ni = 0; ni < 8; ni++) {
                int c0 = wn + ni * 8 + g;
                bf[ni][0] = Bsb[(kk + t4) * BPAD + c0];
                bf[ni][1] = Bsb[(kk + 4 + t4) * BPAD + c0];
            }
            #pragma unroll
            for (int mi = 0; mi < 2; mi++)
                #pragma unroll
                for (int ni = 0; ni < 8; ni++)
                    mma_tf32(acc[mi][ni][0], acc[mi][ni][1], acc[mi][ni][2], acc[mi][ni][3],
                             af[mi][0], af[mi][1], af[mi][2], af[mi][3],
                             bf[ni][0], bf[ni][1]);
        }
        __syncthreads();   // compute done before next iteration overwrites the other buffer
    }

    // ---- epilogue ----
    #pragma unroll
    for (int mi = 0; mi < 2; mi++) {
        #pragma unroll
        for (int half = 0; half < 2; half++) {
            int row = bm + wm + mi * 16 + half * 8 + g;
            if (row >= M) continue;
            #pragma unroll
            for (int ni = 0; ni < 8; ni++) {
                int col = bn + wn + ni * 8 + t4 * 2;
                float v0 = acc[mi][ni][half * 2 + 0] + bias[col];
                float v1 = acc[mi][ni][half * 2 + 1] + bias[col + 1];
                if (EPI == 1) {
                    v0 += res[(size_t)row * N + col];
                    v1 += res[(size_t)row * N + col + 1];
                }
                if (EPI == 2) {
                    v0 = 0.5f * v0 * (1.0f + erff(v0 * 0.70710678118654752f));
                    v1 = 0.5f * v1 * (1.0f + erff(v1 * 0.70710678118654752f));
                }
                float2 o; o.x = v0; o.y = v1;
                *(float2*)(C + (size_t)row * N + col) = o;
            }
        }
    }
}

// ---------------- tensor-core flash attention (tf32, max-free softmax) ----------------
// K/V tiles via cp.async double buffer (raw fp32 bits -> tf32 truncation).
#define KT 32
#define QS 68
#define PS 36

__global__ __launch_bounds__(128) void attn_mma(
    const float* __restrict__ qkv, const int* __restrict__ cu,
    float* __restrict__ out)
{
    __shared__ uint32_t Qs[64 * QS];
    __shared__ uint32_t Ks[2][KT * QS];
    __shared__ uint32_t Vs[2][KT * QS];
    __shared__ uint32_t Ps[4][16 * PS];

    int b = blockIdx.z, h = blockIdx.y, qt = blockIdx.x;
    int s0 = cu[b];
    int len = cu[b + 1] - s0;
    if (qt * 64 >= len) return;

    int tid = threadIdx.x;
    int warp = tid >> 5, lane = tid & 31;
    int g = lane >> 2, t4 = lane & 3;

    // K/V staging: thread -> k-row tid/4, 16 floats at (tid&3)*16
    int krow = tid >> 2;
    int kcol = (tid & 3) * 16;
    uint32_t kDst = (uint32_t)__cvta_generic_to_shared(&Ks[0][krow * QS + kcol]);
    uint32_t vDst = (uint32_t)__cvta_generic_to_shared(&Vs[0][krow * QS + kcol]);
    const uint32_t KBUF = KT * QS * 4;
    int ntile = (len + KT - 1) / KT;

    // prologue: K/V tile 0 -> buf 0
    {
        int gk = krow; if (gk >= len) gk = len - 1;
        const float* base = qkv + (size_t)(s0 + gk) * QKV3 + h * HD + kcol;
        #pragma unroll
        for (int i = 0; i < 4; i++) {
            cpa16(kDst + i * 16, base + D + i * 4);
            cpa16(vDst + i * 16, base + 2 * D + i * 4);
        }
        CP_COMMIT;
    }

    // ---- load Q tile (64x64) to smem: scaled by 1/8, tf32 rounded ----
    {
        int qr = tid >> 1;
        int qc = (tid & 1) * 32;
        int gq = qt * 64 + qr; if (gq >= len) gq = len - 1;
        const float* src = qkv + (size_t)(s0 + gq) * QKV3 + h * HD + qc;
        uint32_t* dst = &Qs[qr * QS + qc];
        #pragma unroll
        for (int i = 0; i < 8; i++) {
            float4 v = *(const float4*)(src + i * 4);
            dst[i * 4 + 0] = f2tf(v.x * 0.125f);
            dst[i * 4 + 1] = f2tf(v.y * 0.125f);
            dst[i * 4 + 2] = f2tf(v.z * 0.125f);
            dst[i * 4 + 3] = f2tf(v.w * 0.125f);
        }
    }
    __syncthreads();

    uint32_t qf[8][4];
    int wq = warp * 16;
    #pragma unroll
    for (int ks = 0; ks < 8; ks++) {
        qf[ks][0] = Qs[(wq + g) * QS + ks * 8 + t4];
        qf[ks][1] = Qs[(wq + g + 8) * QS + ks * 8 + t4];
        qf[ks][2] = Qs[(wq + g) * QS + ks * 8 + 4 + t4];
        qf[ks][3] = Qs[(wq + g + 8) * QS + ks * 8 + 4 + t4];
    }

    float oa[8][4];
    #pragma unroll
    for (int vn = 0; vn < 8; vn++)
        #pragma unroll
        for (int r = 0; r < 4; r++) oa[vn][r] = 0.f;
    float lp0 = 0.f, lp1 = 0.f;

    for (int kt = 0; kt < ntile; kt++) {
        if (kt + 1 < ntile) {
            uint32_t bo = (kt + 1) & 1;
            int gk = (kt + 1) * KT + krow; if (gk >= len) gk = len - 1;
            const float* base = qkv + (size_t)(s0 + gk) * QKV3 + h * HD + kcol;
            #pragma unroll
            for (int i = 0; i < 4; i++) {
                cpa16(kDst + bo * KBUF + i * 16, base + D + i * 4);
                cpa16(vDst + bo * KBUF + i * 16, base + 2 * D + i * 4);
            }
            CP_COMMIT;
            CP_WAIT(1);
        } else {
            CP_WAIT(0);
        }
        __syncthreads();

        const uint32_t* Kb = Ks[kt & 1];
        const uint32_t* Vb = Vs[kt & 1];

        // ---- S = Q K^T ----
        float sa[4][4];
        #pragma unroll
        for (int kn = 0; kn < 4; kn++)
            #pragma unroll
            for (int r = 0; r < 4; r++) sa[kn][r] = 0.f;

        #pragma unroll
        for (int ks = 0; ks < 8; ks++) {
            #pragma unroll
            for (int kn = 0; kn < 4; kn++) {
                uint32_t b0 = Kb[(kn * 8 + g) * QS + ks * 8 + t4];
                uint32_t b1 = Kb[(kn * 8 + g) * QS + ks * 8 + 4 + t4];
                mma_tf32(sa[kn][0], sa[kn][1], sa[kn][2], sa[kn][3],
                         qf[ks][0], qf[ks][1], qf[ks][2], qf[ks][3], b0, b1);
            }
        }

        // ---- P = exp(S), masked; row sums; to smem ----
        uint32_t* pw = Ps[warp];
        #pragma unroll
        for (int kn = 0; kn < 4; kn++) {
            int c0 = kt * KT + kn * 8 + 2 * t4;
            float p0 = (c0     < len) ? __expf(sa[kn][0]) : 0.f;
            float p1 = (c0 + 1 < len) ? __expf(sa[kn][1]) : 0.f;
            float p2 = (c0     < len) ? __expf(sa[kn][2]) : 0.f;
            float p3 = (c0 + 1 < len) ? __expf(sa[kn][3]) : 0.f;
            lp0 += p0 + p1;
            lp1 += p2 + p3;
            pw[g * PS + kn * 8 + 2 * t4]       = f2tf(p0);
            pw[g * PS + kn * 8 + 2 * t4 + 1]   = f2tf(p1);
            pw[(g + 8) * PS + kn * 8 + 2 * t4]     = f2tf(p2);
            pw[(g + 8) * PS + kn * 8 + 2 * t4 + 1] = f2tf(p3);
        }
        __syncwarp();

        // ---- O += P V ----
        #pragma unroll
        for (int ks = 0; ks < 4; ks++) {
            uint32_t a0 = pw[g * PS + ks * 8 + t4];
            uint32_t a1 = pw[(g + 8) * PS + ks * 8 + t4];
            uint32_t a2 = pw[g * PS + ks * 8 + 4 + t4];
            uint32_t a3 = pw[(g + 8) * PS + ks * 8 + 4 + t4];
            #pragma unroll
            for (int vn = 0; vn < 8; vn++) {
                uint32_t b0 = Vb[(ks * 8 + t4) * QS + vn * 8 + g];
                uint32_t b1 = Vb[(ks * 8 + 4 + t4) * QS + vn * 8 + g];
                mma_tf32(oa[vn][0], oa[vn][1], oa[vn][2], oa[vn][3],
                         a0, a1, a2, a3, b0, b1);
            }
        }
        __syncthreads();   // done with this K/V buffer before it is refilled
    }

    lp0 += __shfl_xor_sync(0xFFFFFFFFu, lp0, 1);
    lp0 += __shfl_xor_sync(0xFFFFFFFFu, lp0, 2);
    lp1 += __shfl_xor_sync(0xFFFFFFFFu, lp1, 1);
    lp1 += __shfl_xor_sync(0xFFFFFFFFu, lp1, 2);
    float inv0 = 1.f / lp0, inv1 = 1.f / lp1;

    int q0 = qt * 64 + wq + g;
    int q1 = q0 + 8;
    if (q0 < len) {
        float* op = out + (size_t)(s0 + q0) * D + h * HD;
        #pragma unroll
        for (int vn = 0; vn < 8; vn++) {
            float2 v; v.x = oa[vn][0] * inv0; v.y = oa[vn][1] * inv0;
            *(float2*)(op + vn * 8 + 2 * t4) = v;
        }
    }
    if (q1 < len) {
        float* op = out + (size_t)(s0 + q1) * D + h * HD;
        #pragma unroll
        for (int vn = 0; vn < 8; vn++) {
            float2 v; v.x = oa[vn][2] * inv1; v.y = oa[vn][3] * inv1;
            *(float2*)(op + vn * 8 + 2 * t4) = v;
        }
    }
}

// ---------------- launch ----------------
extern "C" void kernel_launch(void* const* d_in, const int* in_sizes, int n_in,
                              void* d_out, int out_size)
{
    const float* x     = (const float*)d_in[0];
    const int*   cu    = (const int*)  d_in[1];
    const float* g1    = (const float*)d_in[2];
    const float* beta1 = (const float*)d_in[3];
    const float* Wqkv  = (const float*)d_in[4];
    const float* bqkv  = (const float*)d_in[5];
    const float* Wo    = (const float*)d_in[6];
    const float* bo    = (const float*)d_in[7];
    const float* g2    = (const float*)d_in[8];
    const float* beta2 = (const float*)d_in[9];
    const float* W1    = (const float*)d_in[10];
    const float* bfc1  = (const float*)d_in[11];
    const float* W2    = (const float*)d_in[12];
    const float* bfc2  = (const float*)d_in[13];
    float* out = (float*)d_out;

    int total = in_sizes[0] / D;
    int B = in_sizes[1] - 1;

    float *p_ln, *p_qkv, *p_attn, *p_x2, *p_h, *p_m;
    cudaGetSymbolAddress((void**)&p_ln,   g_ln);
    cudaGetSymbolAddress((void**)&p_qkv,  g_qkv);
    cudaGetSymbolAddress((void**)&p_attn, g_attn);
    cudaGetSymbolAddress((void**)&p_x2,   g_x2);
    cudaGetSymbolAddress((void**)&p_h,    g_h);
    cudaGetSymbolAddress((void**)&p_m,    g_m);

    int mtiles = (total + 127) / 128;

    ln_kernel<<<total, 256>>>(x, g1, beta1, p_ln);
    gemm_mma<0><<<dim3(QKV3 / 128, mtiles), 256>>>(p_ln, Wqkv, bqkv, nullptr, p_qkv, total, QKV3, D);
    attn_mma<<<dim3(S_MAX / 64, H, B), 128>>>(p_qkv, cu, p_attn);
    gemm_mma<1><<<dim3(D / 128, mtiles), 256>>>(p_attn, Wo, bo, x, p_x2, total, D, D);
    ln_kernel<<<total, 256>>>(p_x2, g2, beta2, p_h);
    gemm_mma<2><<<dim3(DFF / 128, mtiles), 256>>>(p_h, W1, bfc1, nullptr, p_m, total, DFF, D);
    gemm_mma<1><<<dim3(D / 128, mtiles), 256>>>(p_m, W2, bfc2, p_x2, out, total, D, DFF);
}

// round 6
// speedup vs baseline: 1.6428x; 1.0383x over previous
#include <cuda_runtime.h>
#include <math.h>
#include <stdint.h>

#define D 768
#define H 12
#define HD 64
#define DFF 3072
#define QKV3 2304
#define MAXTOK 8192
#define S_MAX 1024

// ---------------- scratch (static device globals; no allocation) ----------------
__device__ float g_ln[MAXTOK * D];
__device__ float g_qkv[MAXTOK * QKV3];
__device__ float g_attn[MAXTOK * D];
__device__ float g_x2[MAXTOK * D];
__device__ float g_h[MAXTOK * D];
__device__ float g_m[MAXTOK * DFF];

// ---------------- LayerNorm: one block per token row ----------------
__global__ __launch_bounds__(256) void ln_kernel(
    const float* __restrict__ x, const float* __restrict__ g,
    const float* __restrict__ b, float* __restrict__ out)
{
    int row = blockIdx.x;
    const float* xr = x + (size_t)row * D;
    int t = threadIdx.x;

    float v0 = xr[t], v1 = xr[t + 256], v2 = xr[t + 512];
    float s = v0 + v1 + v2;
    float sq = v0 * v0 + v1 * v1 + v2 * v2;

    #pragma unroll
    for (int off = 16; off > 0; off >>= 1) {
        s  += __shfl_xor_sync(0xFFFFFFFFu, s, off);
        sq += __shfl_xor_sync(0xFFFFFFFFu, sq, off);
    }
    __shared__ float ss[8], ssq[8];
    int wid = t >> 5, lid = t & 31;
    if (lid == 0) { ss[wid] = s; ssq[wid] = sq; }
    __syncthreads();
    if (wid == 0) {
        float a = (lid < 8) ? ss[lid] : 0.f;
        float aq = (lid < 8) ? ssq[lid] : 0.f;
        #pragma unroll
        for (int off = 4; off > 0; off >>= 1) {
            a  += __shfl_xor_sync(0xFFFFFFFFu, a, off);
            aq += __shfl_xor_sync(0xFFFFFFFFu, aq, off);
        }
        if (lid == 0) { ss[0] = a; ssq[0] = aq; }
    }
    __syncthreads();
    float mean = ss[0] * (1.0f / D);
    float var = ssq[0] * (1.0f / D) - mean * mean;
    float rstd = rsqrtf(var + 1e-6f);

    float* orow = out + (size_t)row * D;
    orow[t]       = (v0 - mean) * rstd * g[t]       + b[t];
    orow[t + 256] = (v1 - mean) * rstd * g[t + 256] + b[t + 256];
    orow[t + 512] = (v2 - mean) * rstd * g[t + 512] + b[t + 512];
}

// ---------------- tf32 / cp.async helpers ----------------
__device__ __forceinline__ uint32_t f2tf(float f) {
    uint32_t r;
    asm("cvt.rna.tf32.f32 %0, %1;" : "=r"(r) : "f"(f));
    return r;
}

__device__ __forceinline__ void mma_tf32(
    float& c0, float& c1, float& c2, float& c3,
    uint32_t a0, uint32_t a1, uint32_t a2, uint32_t a3,
    uint32_t b0, uint32_t b1)
{
    asm volatile(
        "mma.sync.aligned.m16n8k8.row.col.f32.tf32.tf32.f32 "
        "{%0,%1,%2,%3}, {%4,%5,%6,%7}, {%8,%9}, {%0,%1,%2,%3};"
        : "+f"(c0), "+f"(c1), "+f"(c2), "+f"(c3)
        : "r"(a0), "r"(a1), "r"(a2), "r"(a3), "r"(b0), "r"(b1));
}

__device__ __forceinline__ void cpa16(uint32_t dst, const void* src) {
    asm volatile("cp.async.cg.shared.global [%0], [%1], 16;" :: "r"(dst), "l"(src));
}
#define CP_COMMIT asm volatile("cp.async.commit_group;")
#define CP_WAIT(n) asm volatile("cp.async.wait_group %0;" :: "n"(n))

// ---------------- tensor-core GEMM: 4-stage cp.async pipeline ----------------
// Block tile 128x128x16, 8 warps (4M x 2N), warp tile 32x64.
// One __syncthreads per k-tile: wait(2) -> sync -> prefetch t+3 -> compute t.
// Tiles land as raw fp32 bits; mma.tf32 truncates (fastpath).
#define APAD 20
#define BPAD 136
#define STAGES 4

template <int EPI>
__global__ __launch_bounds__(256, 2) void gemm_mma(
    const float* __restrict__ A, const float* __restrict__ Bm,
    const float* __restrict__ bias, const float* __restrict__ res,
    float* __restrict__ C, int M, int N, int K)
{
    __shared__ uint32_t As[STAGES][128 * APAD];
    __shared__ uint32_t Bs[STAGES][16 * BPAD];

    int tid  = threadIdx.x;
    int warp = tid >> 5, lane = tid & 31;
    int wm = (warp >> 1) * 32;
    int wn = (warp & 1) * 64;
    int g  = lane >> 2;
    int t4 = lane & 3;

    int bm = blockIdx.y * 128;
    int bn = blockIdx.x * 128;

    int aRow = tid >> 1;
    int aCol = (tid & 1) * 8;
    int gaRow = bm + aRow; if (gaRow >= M) gaRow = M - 1;
    const float* Ag = A + (size_t)gaRow * K + aCol;
    int bRow = tid >> 4;
    int bCol = (tid & 15) * 8;
    const float* Bg = Bm + (size_t)bRow * N + bn + bCol;

    uint32_t aDst = (uint32_t)__cvta_generic_to_shared(&As[0][aRow * APAD + aCol]);
    uint32_t bDst = (uint32_t)__cvta_generic_to_shared(&Bs[0][bRow * BPAD + bCol]);
    const uint32_t ABUF = 128 * APAD * 4;
    const uint32_t BBUF = 16 * BPAD * 4;

    float acc[2][8][4];
    #pragma unroll
    for (int mi = 0; mi < 2; mi++)
        #pragma unroll
        for (int ni = 0; ni < 8; ni++)
            #pragma unroll
            for (int r = 0; r < 4; r++) acc[mi][ni][r] = 0.f;

    int T = K >> 4;

    // prologue: tiles 0..2 -> bufs 0..2 (3 committed groups)
    #pragma unroll
    for (int s = 0; s < STAGES - 1; s++) {
        if (s < T) {
            cpa16(aDst + s * ABUF,      Ag + s * 16);
            cpa16(aDst + s * ABUF + 16, Ag + s * 16 + 4);
            cpa16(bDst + s * BBUF,      Bg + (size_t)s * 16 * N);
            cpa16(bDst + s * BBUF + 16, Bg + (size_t)s * 16 * N + 4);
        }
        CP_COMMIT;
    }

    for (int t = 0; t < T; t++) {
        CP_WAIT(STAGES - 2);   // tile t has landed (this thread's view)
        __syncthreads();       // all threads past wait; all done computing buf being refilled

        int pf = t + STAGES - 1;
        if (pf < T) {
            uint32_t bo = pf & (STAGES - 1);
            cpa16(aDst + bo * ABUF,      Ag + pf * 16);
            cpa16(aDst + bo * ABUF + 16, Ag + pf * 16 + 4);
            cpa16(bDst + bo * BBUF,      Bg + (size_t)pf * 16 * N);
            cpa16(bDst + bo * BBUF + 16, Bg + (size_t)pf * 16 * N + 4);
        }
        CP_COMMIT;

        const uint32_t* Asb = As[t & (STAGES - 1)];
        const uint32_t* Bsb = Bs[t & (STAGES - 1)];

        #pragma unroll
        for (int kk = 0; kk < 16; kk += 8) {
            uint32_t af[2][4];
            #pragma unroll
            for (int mi = 0; mi < 2; mi++) {
                int r0 = wm + mi * 16 + g;
                af[mi][0] = Asb[r0 * APAD + kk + t4];
                af[mi][1] = Asb[(r0 + 8) * APAD + kk + t4];
                af[mi][2] = Asb[r0 * APAD + kk + 4 + t4];
                af[mi][3] = Asb[(r0 + 8) * APAD + kk + 4 + t4];
            }
            uint32_t bf[8][2];
            #pragma unroll
            for (int ni = 0; ni < 8; ni++) {
                int c0 = wn + ni * 8 + g;
                bf[ni][0] = Bsb[(kk + t4) * BPAD + c0];
                bf[ni][1] = Bsb[(kk + 4 + t4) * BPAD + c0];
            }
            #pragma unroll
            for (int mi = 0; mi < 2; mi++)
                #pragma unroll
                for (int ni = 0; ni < 8; ni++)
                    mma_tf32(acc[mi][ni][0], acc[mi][ni][1], acc[mi][ni][2], acc[mi][ni][3],
                             af[mi][0], af[mi][1], af[mi][2], af[mi][3],
                             bf[ni][0], bf[ni][1]);
        }
    }

    // ---- epilogue ----
    #pragma unroll
    for (int mi = 0; mi < 2; mi++) {
        #pragma unroll
        for (int half = 0; half < 2; half++) {
            int row = bm + wm + mi * 16 + half * 8 + g;
            if (row >= M) continue;
            #pragma unroll
            for (int ni = 0; ni < 8; ni++) {
                int col = bn + wn + ni * 8 + t4 * 2;
                float v0 = acc[mi][ni][half * 2 + 0] + bias[col];
                float v1 = acc[mi][ni][half * 2 + 1] + bias[col + 1];
                if (EPI == 1) {
                    v0 += res[(size_t)row * N + col];
                    v1 += res[(size_t)row * N + col + 1];
                }
                if (EPI == 2) {
                    v0 = 0.5f * v0 * (1.0f + erff(v0 * 0.70710678118654752f));
                    v1 = 0.5f * v1 * (1.0f + erff(v1 * 0.70710678118654752f));
                }
                float2 o; o.x = v0; o.y = v1;
                *(float2*)(C + (size_t)row * N + col) = o;
            }
        }
    }
}

// ---------------- tensor-core flash attention (tf32, max-free softmax) ----------------
// (unchanged from R5 — isolate the GEMM pipeline variable)
#define KT 32
#define QS 68
#define PS 36

__global__ __launch_bounds__(128) void attn_mma(
    const float* __restrict__ qkv, const int* __restrict__ cu,
    float* __restrict__ out)
{
    __shared__ uint32_t Qs[64 * QS];
    __shared__ uint32_t Ks[2][KT * QS];
    __shared__ uint32_t Vs[2][KT * QS];
    __shared__ uint32_t Ps[4][16 * PS];

    int b = blockIdx.z, h = blockIdx.y, qt = blockIdx.x;
    int s0 = cu[b];
    int len = cu[b + 1] - s0;
    if (qt * 64 >= len) return;

    int tid = threadIdx.x;
    int warp = tid >> 5, lane = tid & 31;
    int g = lane >> 2, t4 = lane & 3;

    int krow = tid >> 2;
    int kcol = (tid & 3) * 16;
    uint32_t kDst = (uint32_t)__cvta_generic_to_shared(&Ks[0][krow * QS + kcol]);
    uint32_t vDst = (uint32_t)__cvta_generic_to_shared(&Vs[0][krow * QS + kcol]);
    const uint32_t KBUF = KT * QS * 4;
    int ntile = (len + KT - 1) / KT;

    {
        int gk = krow; if (gk >= len) gk = len - 1;
        const float* base = qkv + (size_t)(s0 + gk) * QKV3 + h * HD + kcol;
        #pragma unroll
        for (int i = 0; i < 4; i++) {
            cpa16(kDst + i * 16, base + D + i * 4);
            cpa16(vDst + i * 16, base + 2 * D + i * 4);
        }
        CP_COMMIT;
    }

    {
        int qr = tid >> 1;
        int qc = (tid & 1) * 32;
        int gq = qt * 64 + qr; if (gq >= len) gq = len - 1;
        const float* src = qkv + (size_t)(s0 + gq) * QKV3 + h * HD + qc;
        uint32_t* dst = &Qs[qr * QS + qc];
        #pragma unroll
        for (int i = 0; i < 8; i++) {
            float4 v = *(const float4*)(src + i * 4);
            dst[i * 4 + 0] = f2tf(v.x * 0.125f);
            dst[i * 4 + 1] = f2tf(v.y * 0.125f);
            dst[i * 4 + 2] = f2tf(v.z * 0.125f);
            dst[i * 4 + 3] = f2tf(v.w * 0.125f);
        }
    }
    __syncthreads();

    uint32_t qf[8][4];
    int wq = warp * 16;
    #pragma unroll
    for (int ks = 0; ks < 8; ks++) {
        qf[ks][0] = Qs[(wq + g) * QS + ks * 8 + t4];
        qf[ks][1] = Qs[(wq + g + 8) * QS + ks * 8 + t4];
        qf[ks][2] = Qs[(wq + g) * QS + ks * 8 + 4 + t4];
        qf[ks][3] = Qs[(wq + g + 8) * QS + ks * 8 + 4 + t4];
    }

    float oa[8][4];
    #pragma unroll
    for (int vn = 0; vn < 8; vn++)
        #pragma unroll
        for (int r = 0; r < 4; r++) oa[vn][r] = 0.f;
    float lp0 = 0.f, lp1 = 0.f;

    for (int kt = 0; kt < ntile; kt++) {
        if (kt + 1 < ntile) {
            uint32_t bo = (kt + 1) & 1;
            int gk = (kt + 1) * KT + krow; if (gk >= len) gk = len - 1;
            const float* base = qkv + (size_t)(s0 + gk) * QKV3 + h * HD + kcol;
            #pragma unroll
            for (int i = 0; i < 4; i++) {
                cpa16(kDst + bo * KBUF + i * 16, base + D + i * 4);
                cpa16(vDst + bo * KBUF + i * 16, base + 2 * D + i * 4);
            }
            CP_COMMIT;
            CP_WAIT(1);
        } else {
            CP_WAIT(0);
        }
        __syncthreads();

        const uint32_t* Kb = Ks[kt & 1];
        const uint32_t* Vb = Vs[kt & 1];

        float sa[4][4];
        #pragma unroll
        for (int kn = 0; kn < 4; kn++)
            #pragma unroll
            for (int r = 0; r < 4; r++) sa[kn][r] = 0.f;

        #pragma unroll
        for (int ks = 0; ks < 8; ks++) {
            #pragma unroll
            for (int kn = 0; kn < 4; kn++) {
                uint32_t b0 = Kb[(kn * 8 + g) * QS + ks * 8 + t4];
                uint32_t b1 = Kb[(kn * 8 + g) * QS + ks * 8 + 4 + t4];
                mma_tf32(sa[kn][0], sa[kn][1], sa[kn][2], sa[kn][3],
                         qf[ks][0], qf[ks][1], qf[ks][2], qf[ks][3], b0, b1);
            }
        }

        uint32_t* pw = Ps[warp];
        #pragma unroll
        for (int kn = 0; kn < 4; kn++) {
            int c0 = kt * KT + kn * 8 + 2 * t4;
            float p0 = (c0     < len) ? __expf(sa[kn][0]) : 0.f;
            float p1 = (c0 + 1 < len) ? __expf(sa[kn][1]) : 0.f;
            float p2 = (c0     < len) ? __expf(sa[kn][2]) : 0.f;
            float p3 = (c0 + 1 < len) ? __expf(sa[kn][3]) : 0.f;
            lp0 += p0 + p1;
            lp1 += p2 + p3;
            pw[g * PS + kn * 8 + 2 * t4]       = f2tf(p0);
            pw[g * PS + kn * 8 + 2 * t4 + 1]   = f2tf(p1);
            pw[(g + 8) * PS + kn * 8 + 2 * t4]     = f2tf(p2);
            pw[(g + 8) * PS + kn * 8 + 2 * t4 + 1] = f2tf(p3);
        }
        __syncwarp();

        #pragma unroll
        for (int ks = 0; ks < 4; ks++) {
            uint32_t a0 = pw[g * PS + ks * 8 + t4];
            uint32_t a1 = pw[(g + 8) * PS + ks * 8 + t4];
            uint32_t a2 = pw[g * PS + ks * 8 + 4 + t4];
            uint32_t a3 = pw[(g + 8) * PS + ks * 8 + 4 + t4];
            #pragma unroll
            for (int vn = 0; vn < 8; vn++) {
                uint32_t b0 = Vb[(ks * 8 + t4) * QS + vn * 8 + g];
                uint32_t b1 = Vb[(ks * 8 + 4 + t4) * QS + vn * 8 + g];
                mma_tf32(oa[vn][0], oa[vn][1], oa[vn][2], oa[vn][3],
                         a0, a1, a2, a3, b0, b1);
            }
        }
        __syncthreads();
    }

    lp0 += __shfl_xor_sync(0xFFFFFFFFu, lp0, 1);
    lp0 += __shfl_xor_sync(0xFFFFFFFFu, lp0, 2);
    lp1 += __shfl_xor_sync(0xFFFFFFFFu, lp1, 1);
    lp1 += __shfl_xor_sync(0xFFFFFFFFu, lp1, 2);
    float inv0 = 1.f / lp0, inv1 = 1.f / lp1;

    int q0 = qt * 64 + wq + g;
    int q1 = q0 + 8;
    if (q0 < len) {
        float* op = out + (size_t)(s0 + q0) * D + h * HD;
        #pragma unroll
        for (int vn = 0; vn < 8; vn++) {
            float2 v; v.x = oa[vn][0] * inv0; v.y = oa[vn][1] * inv0;
            *(float2*)(op + vn * 8 + 2 * t4) = v;
        }
    }
    if (q1 < len) {
        float* op = out + (size_t)(s0 + q1) * D + h * HD;
        #pragma unroll
        for (int vn = 0; vn < 8; vn++) {
            float2 v; v.x = oa[vn][2] * inv1; v.y = oa[vn][3] * inv1;
            *(float2*)(op + vn * 8 + 2 * t4) = v;
        }
    }
}

// ---------------- launch ----------------
extern "C" void kernel_launch(void* const* d_in, const int* in_sizes, int n_in,
                              void* d_out, int out_size)
{
    const float* x     = (const float*)d_in[0];
    const int*   cu    = (const int*)  d_in[1];
    const float* g1    = (const float*)d_in[2];
    const float* beta1 = (const float*)d_in[3];
    const float* Wqkv  = (const float*)d_in[4];
    const float* bqkv  = (const float*)d_in[5];
    const float* Wo    = (const float*)d_in[6];
    const float* bo    = (const float*)d_in[7];
    const float* g2    = (const float*)d_in[8];
    const float* beta2 = (const float*)d_in[9];
    const float* W1    = (const float*)d_in[10];
    const float* bfc1  = (const float*)d_in[11];
    const float* W2    = (const float*)d_in[12];
    const float* bfc2  = (const float*)d_in[13];
    float* out = (float*)d_out;

    int total = in_sizes[0] / D;
    int B = in_sizes[1] - 1;

    float *p_ln, *p_qkv, *p_attn, *p_x2, *p_h, *p_m;
    cudaGetSymbolAddress((void**)&p_ln,   g_ln);
    cudaGetSymbolAddress((void**)&p_qkv,  g_qkv);
    cudaGetSymbolAddress((void**)&p_attn, g_attn);
    cudaGetSymbolAddress((void**)&p_x2,   g_x2);
    cudaGetSymbolAddress((void**)&p_h,    g_h);
    cudaGetSymbolAddress((void**)&p_m,    g_m);

    int mtiles = (total + 127) / 128;

    ln_kernel<<<total, 256>>>(x, g1, beta1, p_ln);
    gemm_mma<0><<<dim3(QKV3 / 128, mtiles), 256>>>(p_ln, Wqkv, bqkv, nullptr, p_qkv, total, QKV3, D);
    attn_mma<<<dim3(S_MAX / 64, H, B), 128>>>(p_qkv, cu, p_attn);
    gemm_mma<1><<<dim3(D / 128, mtiles), 256>>>(p_attn, Wo, bo, x, p_x2, total, D, D);
    ln_kernel<<<total, 256>>>(p_x2, g2, beta2, p_h);
    gemm_mma<2><<<dim3(DFF / 128, mtiles), 256>>>(p_h, W1, bfc1, nullptr, p_m, total, DFF, D);
    gemm_mma<1><<<dim3(D / 128, mtiles), 256>>>(p_m, W2, bfc2, p_x2, out, total, D, DFF);
}